// round 10
// baseline (speedup 1.0000x reference)
#include <cuda_runtime.h>
#include <cuda_bf16.h>
#include <cstdint>

// conv_layer_65000035058096 — 3xBF16 mma.sync gather-GEMM (baseline PTX)
// D = xh*wh + xh*wl + xl*wh (bf16 hi/lo split, fp32 accum, err ~2^-18)
// R10: 32-k chunks, triple-buffer ring, ONE barrier per chunk (14 total).

#define V_TOT 163842
#define NKS 28            // k-steps of 16
#define NCH 14            // chunks of 32 k
#define SA 36             // As row stride in words (32 data + 4 pad) -> <=2-way banks

// B fragments, mma m16n8k16 register layout, hi/lo packed:
// g_Bf[(s*8+nb)*32 + lane] = {bh0, bh1, bl0, bl1},  s = k-step 0..27
__device__ uint4 g_Bf[NKS * 8 * 32];

__device__ __forceinline__ uint32_t pack_bf16_hi_lo(float hi_elem, float lo_elem) {
    uint32_t r;
    asm("cvt.rn.bf16x2.f32 %0, %1, %2;" : "=r"(r) : "f"(hi_elem), "f"(lo_elem));
    return r;
}

__global__ void pack_B_kernel(const float* __restrict__ W) {
    int idx = blockIdx.x * blockDim.x + threadIdx.x;   // 28*8*32 = 7168
    if (idx < NKS * 8 * 32) {
        int l = idx & 31, nbk = (idx >> 5) & 7, s = idx >> 8;
        int g = l >> 2, tig = l & 3;
        int o = nbk * 8 + g;
        const float* wr = W + o * 448 + s * 16 + 2 * tig;
        float v[4] = { wr[0], wr[1], wr[8], wr[9] };
        float h[4], lo[4];
#pragma unroll
        for (int i = 0; i < 4; ++i) {
            __nv_bfloat16 hb = __float2bfloat16_rn(v[i]);
            h[i] = __bfloat162float(hb);
            lo[i] = v[i] - h[i];
        }
        uint4 r;
        r.x = pack_bf16_hi_lo(h[1], h[0]);
        r.y = pack_bf16_hi_lo(h[3], h[2]);
        r.z = pack_bf16_hi_lo(lo[1], lo[0]);
        r.w = pack_bf16_hi_lo(lo[3], lo[2]);
        g_Bf[idx] = r;
    }
}

__device__ __forceinline__ void cpa16(uint32_t dst, const void* src) {
    asm volatile("cp.async.cg.shared.global [%0], [%1], 16;" :: "r"(dst), "l"(src) : "memory");
}
__device__ __forceinline__ uint32_t smem_u32(const void* p) {
    uint32_t a;
    asm("{ .reg .u64 t; cvta.to.shared.u64 t, %1; cvt.u32.u64 %0, t; }" : "=r"(a) : "l"(p));
    return a;
}
__device__ __forceinline__ void cvt_pair(float2 p, uint32_t& hi2, uint32_t& lo2) {
    uint32_t h;
    asm("cvt.rn.bf16x2.f32 %0, %1, %2;" : "=r"(h) : "f"(p.y), "f"(p.x));
    float hx = __uint_as_float(h << 16);
    float hy = __uint_as_float(h & 0xFFFF0000u);
    float lx = p.x - hx, ly = p.y - hy;
    uint32_t l;
    asm("cvt.rn.bf16x2.f32 %0, %1, %2;" : "=r"(l) : "f"(ly), "f"(lx));
    hi2 = h; lo2 = l;
}
#define MMA(c, a, b0, b1) asm volatile( \
    "mma.sync.aligned.m16n8k16.row.col.f32.bf16.bf16.f32 " \
    "{%0,%1,%2,%3}, {%4,%5,%6,%7}, {%8,%9}, {%0,%1,%2,%3};" \
    : "+f"((c)[0]), "+f"((c)[1]), "+f"((c)[2]), "+f"((c)[3]) \
    : "r"((a)[0]), "r"((a)[1]), "r"((a)[2]), "r"((a)[3]), "r"(b0), "r"(b1))

// dynamic smem: As 3*128*36*4 = 55296 | Bs 3*8192 = 24576 | nbs 3584  -> 83456 B
#define OFF_BS  55296
#define OFF_NBS 79872
#define SMEM_REQ 83456

__global__ __launch_bounds__(256, 1)
void sconv_bf16(const float* __restrict__ x,
                const int* __restrict__ nb,
                const float* __restrict__ bias,
                float* __restrict__ out) {
    extern __shared__ char dsm[];
    float* As  = (float*)dsm;                      // [3][128*SA]
    uint4* Bs  = (uint4*)(dsm + OFF_BS);           // [3][2][256]
    int*   nbs = (int*)(dsm + OFF_NBS);            // [7][128]
    const uint32_t asb = smem_u32(dsm);
    const uint32_t bsb = asb + OFF_BS;

    const int t    = threadIdx.x;
    const int lane = t & 31;
    const int w    = t >> 5;
    const int g    = lane >> 2;
    const int tig  = lane & 3;
    const int wv   = w << 4;
    const int batch = blockIdx.y;
    const int v0    = blockIdx.x * 128;
    const long long xbase = (long long)batch * V_TOT;

    // ---- stage neighbor indices: nbs[j*128 + r]
#pragma unroll
    for (int i = 0; i < 4; ++i) {
        int idx = t + (i << 8);
        if (idx < 896) {
            int r = idx & 127, j = idx >> 7;
            int vv = v0 + r; if (vv >= V_TOT) vv = V_TOT - 1;
            nbs[idx] = nb[vv * 7 + j];
        }
    }
    __syncthreads();

    float acc[8][4];
#pragma unroll
    for (int n = 0; n < 8; ++n)
#pragma unroll
        for (int e = 0; e < 4; ++e) acc[n][e] = 0.0f;

    // staging mapping: A row rS (t>>1), 4 of 8 quads; B: 2 uint4 tasks
    const int rS  = t >> 1;
    const int qS0 = (t & 1) << 2;

    // ---- prologue: stage chunks 0 and 1 (both j=0)
#pragma unroll
    for (int pc = 0; pc < 2; ++pc) {
        const int kb = pc << 5;
        const int r  = nbs[rS];
        const uint32_t ad = asb + pc * (128 * SA * 4);
#pragma unroll
        for (int i = 0; i < 4; ++i) {
            int q = qS0 + i;
            cpa16(ad + (rS * SA + (q << 2)) * 4,
                  x + ((xbase + r) << 6) + kb + (q << 2));
        }
#pragma unroll
        for (int i = 0; i < 2; ++i) {
            int ks = i;   // slot = t
            cpa16(bsb + pc * 8192 + ks * 4096 + t * 16,
                  (const char*)g_Bf + ((2 * pc + ks) * 256 + t) * 16);
        }
        asm volatile("cp.async.commit_group;" ::: "memory");
    }

    for (int c = 0; c < NCH; ++c) {
        const int buf = c % 3;

        if (c < NCH - 1) asm volatile("cp.async.wait_group 1;" ::: "memory");
        else             asm volatile("cp.async.wait_group 0;" ::: "memory");
        __syncthreads();   // stage c visible to all; compute c-1 done by all

        // ---- stage chunk c+2 into buf (c+2)%3
        if (c + 2 < NCH) {
            const int cn = c + 2;
            const int j  = cn >> 1;
            const int kb = (cn & 1) << 5;
            const int bn = cn % 3;
            const int r  = nbs[j * 128 + rS];
            const uint32_t ad = asb + bn * (128 * SA * 4);
#pragma unroll
            for (int i = 0; i < 4; ++i) {
                int q = qS0 + i;
                cpa16(ad + (rS * SA + (q << 2)) * 4,
                      x + ((xbase + r) << 6) + kb + (q << 2));
            }
#pragma unroll
            for (int i = 0; i < 2; ++i) {
                int ks = i;
                cpa16(bsb + bn * 8192 + ks * 4096 + t * 16,
                      (const char*)g_Bf + ((2 * cn + ks) * 256 + t) * 16);
            }
            asm volatile("cp.async.commit_group;" ::: "memory");
        }

        // ---- compute chunk c: 2 k-steps x (4 cvt_pair + 24 MMA)
        const float* aB = As + buf * (128 * SA);
        const uint4* bC = Bs + buf * 512;
        const int r0 = (wv + g) * SA;
        const int r1 = (wv + g + 8) * SA;
#pragma unroll
        for (int ks = 0; ks < 2; ++ks) {
            const int col = (ks << 4) + 2 * tig;
            float2 p00 = *reinterpret_cast<const float2*>(aB + r0 + col);
            float2 p10 = *reinterpret_cast<const float2*>(aB + r1 + col);
            float2 p01 = *reinterpret_cast<const float2*>(aB + r0 + col + 8);
            float2 p11 = *reinterpret_cast<const float2*>(aB + r1 + col + 8);
            uint32_t ah[4], al[4];
            cvt_pair(p00, ah[0], al[0]);
            cvt_pair(p10, ah[1], al[1]);
            cvt_pair(p01, ah[2], al[2]);
            cvt_pair(p11, ah[3], al[3]);

            const uint4* bK = bC + (ks << 8);
#pragma unroll
            for (int nblk = 0; nblk < 8; ++nblk) {
                uint4 bf = bK[(nblk << 5) + lane];
                MMA(acc[nblk], ah, bf.x, bf.y);   // xh * wh
                MMA(acc[nblk], ah, bf.z, bf.w);   // xh * wl
                MMA(acc[nblk], al, bf.x, bf.y);   // xl * wh
            }
        }
    }

    // ---- epilogue: D frags -> global (+bias)
    const int vr0 = v0 + wv + g;
    const int vr1 = vr0 + 8;
#pragma unroll
    for (int nblk = 0; nblk < 8; ++nblk) {
        const int n = (nblk << 3) + 2 * tig;
        const float2 b2 = *reinterpret_cast<const float2*>(bias + n);
        if (vr0 < V_TOT)
            *reinterpret_cast<float2*>(out + ((xbase + vr0) << 6) + n) =
                make_float2(acc[nblk][0] + b2.x, acc[nblk][1] + b2.y);
        if (vr1 < V_TOT)
            *reinterpret_cast<float2*>(out + ((xbase + vr1) << 6) + n) =
                make_float2(acc[nblk][2] + b2.x, acc[nblk][3] + b2.y);
    }
}

extern "C" void kernel_launch(void* const* d_in, const int* in_sizes, int n_in,
                              void* d_out, int out_size) {
    const float* x   = (const float*)d_in[0];   // (2, V, 64) f32
    const int*   nbi = (const int*)d_in[1];     // (V*7,) i32
    const float* W   = (const float*)d_in[2];   // (64, 448) f32
    const float* b   = (const float*)d_in[3];   // (64,) f32
    float*       out = (float*)d_out;           // (2, V, 64) f32

    cudaFuncSetAttribute(sconv_bf16, cudaFuncAttributeMaxDynamicSharedMemorySize, SMEM_REQ);

    pack_B_kernel<<<(NKS * 8 * 32 + 255) / 256, 256>>>(W);

    dim3 grid((V_TOT + 127) / 128, 2);
    sconv_bf16<<<grid, 256, SMEM_REQ>>>(x, nbi, b, out);
}

// round 11
// speedup vs baseline: 1.0825x; 1.0825x over previous
#include <cuda_runtime.h>
#include <cuda_bf16.h>
#include <cstdint>

// conv_layer_65000035058096 — 3xBF16 mma.sync gather-GEMM (baseline PTX)
// D = xh*wh + xh*wl + xl*wh (bf16 hi/lo split, fp32 accum, err ~2^-18)
// R11 = R9 (226us champion) with occupancy forced to 3 CTAs/SM (84 regs).

#define V_TOT 163842
#define NCH 28            // k-steps of 16
#define SA 20             // As row stride in words (16 data + 4 pad)

// B fragments, mma m16n8k16 register layout, hi/lo packed:
// g_Bf[(s*8+nb)*32 + lane] = {bh0, bh1, bl0, bl1}
__device__ uint4 g_Bf[NCH * 8 * 32];

__device__ __forceinline__ uint32_t pack_bf16_hi_lo(float hi_elem, float lo_elem) {
    uint32_t r;
    asm("cvt.rn.bf16x2.f32 %0, %1, %2;" : "=r"(r) : "f"(hi_elem), "f"(lo_elem));
    return r;
}

__global__ void pack_B_kernel(const float* __restrict__ W) {
    int idx = blockIdx.x * blockDim.x + threadIdx.x;   // 7168
    if (idx < NCH * 8 * 32) {
        int l = idx & 31, nbk = (idx >> 5) & 7, s = idx >> 8;
        int g = l >> 2, tig = l & 3;
        int o = nbk * 8 + g;
        const float* wr = W + o * 448 + s * 16 + 2 * tig;
        float v[4] = { wr[0], wr[1], wr[8], wr[9] };
        float h[4], lo[4];
#pragma unroll
        for (int i = 0; i < 4; ++i) {
            __nv_bfloat16 hb = __float2bfloat16_rn(v[i]);
            h[i] = __bfloat162float(hb);
            lo[i] = v[i] - h[i];
        }
        uint4 r;
        r.x = pack_bf16_hi_lo(h[1], h[0]);
        r.y = pack_bf16_hi_lo(h[3], h[2]);
        r.z = pack_bf16_hi_lo(lo[1], lo[0]);
        r.w = pack_bf16_hi_lo(lo[3], lo[2]);
        g_Bf[idx] = r;
    }
}

__device__ __forceinline__ void cpa16(uint32_t dst, const void* src) {
    asm volatile("cp.async.cg.shared.global [%0], [%1], 16;" :: "r"(dst), "l"(src) : "memory");
}
__device__ __forceinline__ uint32_t smem_u32(const void* p) {
    uint32_t a;
    asm("{ .reg .u64 t; cvta.to.shared.u64 t, %1; cvt.u32.u64 %0, t; }" : "=r"(a) : "l"(p));
    return a;
}
__device__ __forceinline__ void cvt_pair(float2 p, uint32_t& hi2, uint32_t& lo2) {
    uint32_t h;
    asm("cvt.rn.bf16x2.f32 %0, %1, %2;" : "=r"(h) : "f"(p.y), "f"(p.x));
    float hx = __uint_as_float(h << 16);
    float hy = __uint_as_float(h & 0xFFFF0000u);
    float lx = p.x - hx, ly = p.y - hy;
    uint32_t l;
    asm("cvt.rn.bf16x2.f32 %0, %1, %2;" : "=r"(l) : "f"(ly), "f"(lx));
    hi2 = h; lo2 = l;
}
#define MMA(c, a, b0, b1) asm volatile( \
    "mma.sync.aligned.m16n8k16.row.col.f32.bf16.bf16.f32 " \
    "{%0,%1,%2,%3}, {%4,%5,%6,%7}, {%8,%9}, {%0,%1,%2,%3};" \
    : "+f"((c)[0]), "+f"((c)[1]), "+f"((c)[2]), "+f"((c)[3]) \
    : "r"((a)[0]), "r"((a)[1]), "r"((a)[2]), "r"((a)[3]), "r"(b0), "r"(b1))

__global__ __launch_bounds__(256, 3)
void sconv_bf16(const float* __restrict__ x,
                const int* __restrict__ nb,
                const float* __restrict__ bias,
                float* __restrict__ out) {
    __shared__ float As[2][128 * SA];   // 2 x 10240 B
    __shared__ uint4 Bs[2][8 * 32];     // 2 x 4096 B
    __shared__ int   nbs[896];          // [j][row]

    const int t    = threadIdx.x;
    const int lane = t & 31;
    const int w    = t >> 5;
    const int g    = lane >> 2;
    const int tig  = lane & 3;
    const int wv   = w << 4;
    const int batch = blockIdx.y;
    const int v0    = blockIdx.x * 128;
    const long long xbase = (long long)batch * V_TOT;

    // ---- stage neighbor indices: nbs[j*128 + r]
#pragma unroll
    for (int i = 0; i < 4; ++i) {
        int idx = t + (i << 8);
        if (idx < 896) {
            int r = idx & 127, j = idx >> 7;
            int vv = v0 + r; if (vv >= V_TOT) vv = V_TOT - 1;
            nbs[idx] = nb[vv * 7 + j];
        }
    }
    __syncthreads();

    uint32_t asb[2] = { smem_u32(&As[0][0]), smem_u32(&As[1][0]) };
    uint32_t bsb[2] = { smem_u32(&Bs[0][0]), smem_u32(&Bs[1][0]) };

    float acc[8][4];
#pragma unroll
    for (int n = 0; n < 8; ++n)
#pragma unroll
        for (int e = 0; e < 4; ++e) acc[n][e] = 0.0f;

    // staging mapping: 512 (row,quad) tasks over 256 threads x 2
    const int rS  = t >> 1;
    const int qS0 = (t & 1) << 1;

    // prologue: stage chunk 0
    {
#pragma unroll
        for (int i = 0; i < 2; ++i) {
            int q = qS0 + i;
            cpa16(asb[0] + (rS * SA + (q << 2)) * 4,
                  x + ((xbase + nbs[rS]) << 6) + (q << 2));
        }
        cpa16(bsb[0] + t * 16, (const char*)g_Bf + t * 16);
        asm volatile("cp.async.commit_group;" ::: "memory");
    }

    for (int c = 0; c < NCH; ++c) {
        const int buf = c & 1;

        if (c + 1 < NCH) {
            const int cn = c + 1;
            const int j  = cn >> 2;
            const int kb = (cn & 3) << 4;
            const int bn = cn & 1;
            const int row = nbs[j * 128 + rS];
#pragma unroll
            for (int i = 0; i < 2; ++i) {
                int q = qS0 + i;
                cpa16(asb[bn] + (rS * SA + (q << 2)) * 4,
                      x + ((xbase + row) << 6) + kb + (q << 2));
            }
            cpa16(bsb[bn] + t * 16, (const char*)g_Bf + cn * 4096 + t * 16);
            asm volatile("cp.async.commit_group;" ::: "memory");
            asm volatile("cp.async.wait_group 1;" ::: "memory");
        } else {
            asm volatile("cp.async.wait_group 0;" ::: "memory");
        }
        __syncthreads();

        // ---- compute chunk c
        const float* aB = &As[buf][0];
        const int r0 = (wv + g) * SA;
        const int r1 = (wv + g + 8) * SA;
        float2 p00 = *reinterpret_cast<const float2*>(aB + r0 + 2 * tig);
        float2 p10 = *reinterpret_cast<const float2*>(aB + r1 + 2 * tig);
        float2 p01 = *reinterpret_cast<const float2*>(aB + r0 + 2 * tig + 8);
        float2 p11 = *reinterpret_cast<const float2*>(aB + r1 + 2 * tig + 8);
        uint32_t ah[4], al[4];
        cvt_pair(p00, ah[0], al[0]);
        cvt_pair(p10, ah[1], al[1]);
        cvt_pair(p01, ah[2], al[2]);
        cvt_pair(p11, ah[3], al[3]);

        const uint4* bB = &Bs[buf][0];
#pragma unroll
        for (int nblk = 0; nblk < 8; ++nblk) {
            uint4 bf = bB[(nblk << 5) + lane];
            MMA(acc[nblk], ah, bf.x, bf.y);   // xh * wh
            MMA(acc[nblk], ah, bf.z, bf.w);   // xh * wl
            MMA(acc[nblk], al, bf.x, bf.y);   // xl * wh
        }
        __syncthreads();   // done reading buf before it is re-staged
    }

    // ---- epilogue: D frags -> global (+bias)
    const int vr0 = v0 + wv + g;
    const int vr1 = vr0 + 8;
#pragma unroll
    for (int nblk = 0; nblk < 8; ++nblk) {
        const int n = (nblk << 3) + 2 * tig;
        const float2 b2 = *reinterpret_cast<const float2*>(bias + n);
        if (vr0 < V_TOT)
            *reinterpret_cast<float2*>(out + ((xbase + vr0) << 6) + n) =
                make_float2(acc[nblk][0] + b2.x, acc[nblk][1] + b2.y);
        if (vr1 < V_TOT)
            *reinterpret_cast<float2*>(out + ((xbase + vr1) << 6) + n) =
                make_float2(acc[nblk][2] + b2.x, acc[nblk][3] + b2.y);
    }
}

extern "C" void kernel_launch(void* const* d_in, const int* in_sizes, int n_in,
                              void* d_out, int out_size) {
    const float* x   = (const float*)d_in[0];   // (2, V, 64) f32
    const int*   nbi = (const int*)d_in[1];     // (V*7,) i32
    const float* W   = (const float*)d_in[2];   // (64, 448) f32
    const float* b   = (const float*)d_in[3];   // (64,) f32
    float*       out = (float*)d_out;           // (2, V, 64) f32

    pack_B_kernel<<<(NCH * 8 * 32 + 255) / 256, 256>>>(W);

    dim3 grid((V_TOT + 127) / 128, 2);
    sconv_bf16<<<grid, 256>>>(x, nbi, b, out);
}

// round 12
// speedup vs baseline: 1.1593x; 1.0710x over previous
#include <cuda_runtime.h>
#include <cuda_bf16.h>
#include <cstdint>

// conv_layer_65000035058096 — 3xBF16 mma.sync gather-GEMM (baseline PTX)
// D = xh*wh + xh*wl + xl*wh (bf16 hi/lo split, fp32 accum, err ~2^-18)
// R12: warp tile m32 x n64 (B fragments amortized over 2x vertices),
// CTA = 256 vertices, double-buffered cp.async, 16-k chunks.

#define V_TOT 163842
#define NCH 28            // k-steps of 16
#define SA 20             // As row stride in words (16 data + 4 pad)
#define TILE_V 256

// B fragments, mma m16n8k16 register layout, hi/lo packed:
// g_Bf[(s*8+nb)*32 + lane] = {bh0, bh1, bl0, bl1}
__device__ uint4 g_Bf[NCH * 8 * 32];

__device__ __forceinline__ uint32_t pack_bf16_hi_lo(float hi_elem, float lo_elem) {
    uint32_t r;
    asm("cvt.rn.bf16x2.f32 %0, %1, %2;" : "=r"(r) : "f"(hi_elem), "f"(lo_elem));
    return r;
}

__global__ void pack_B_kernel(const float* __restrict__ W) {
    int idx = blockIdx.x * blockDim.x + threadIdx.x;   // 7168
    if (idx < NCH * 8 * 32) {
        int l = idx & 31, nbk = (idx >> 5) & 7, s = idx >> 8;
        int g = l >> 2, tig = l & 3;
        int o = nbk * 8 + g;
        const float* wr = W + o * 448 + s * 16 + 2 * tig;
        float v[4] = { wr[0], wr[1], wr[8], wr[9] };
        float h[4], lo[4];
#pragma unroll
        for (int i = 0; i < 4; ++i) {
            __nv_bfloat16 hb = __float2bfloat16_rn(v[i]);
            h[i] = __bfloat162float(hb);
            lo[i] = v[i] - h[i];
        }
        uint4 r;
        r.x = pack_bf16_hi_lo(h[1], h[0]);
        r.y = pack_bf16_hi_lo(h[3], h[2]);
        r.z = pack_bf16_hi_lo(lo[1], lo[0]);
        r.w = pack_bf16_hi_lo(lo[3], lo[2]);
        g_Bf[idx] = r;
    }
}

__device__ __forceinline__ void cpa16(uint32_t dst, const void* src) {
    asm volatile("cp.async.cg.shared.global [%0], [%1], 16;" :: "r"(dst), "l"(src) : "memory");
}
__device__ __forceinline__ uint32_t smem_u32(const void* p) {
    uint32_t a;
    asm("{ .reg .u64 t; cvta.to.shared.u64 t, %1; cvt.u32.u64 %0, t; }" : "=r"(a) : "l"(p));
    return a;
}
__device__ __forceinline__ void cvt_pair(float2 p, uint32_t& hi2, uint32_t& lo2) {
    uint32_t h;
    asm("cvt.rn.bf16x2.f32 %0, %1, %2;" : "=r"(h) : "f"(p.y), "f"(p.x));
    float hx = __uint_as_float(h << 16);
    float hy = __uint_as_float(h & 0xFFFF0000u);
    float lx = p.x - hx, ly = p.y - hy;
    uint32_t l;
    asm("cvt.rn.bf16x2.f32 %0, %1, %2;" : "=r"(l) : "f"(ly), "f"(lx));
    hi2 = h; lo2 = l;
}
#define MMA(c, a, b0, b1) asm volatile( \
    "mma.sync.aligned.m16n8k16.row.col.f32.bf16.bf16.f32 " \
    "{%0,%1,%2,%3}, {%4,%5,%6,%7}, {%8,%9}, {%0,%1,%2,%3};" \
    : "+f"((c)[0]), "+f"((c)[1]), "+f"((c)[2]), "+f"((c)[3]) \
    : "r"((a)[0]), "r"((a)[1]), "r"((a)[2]), "r"((a)[3]), "r"(b0), "r"(b1))

// dynamic smem: As 2*256*20*4 = 40960 | Bs 2*4096 = 8192 | nbs 1792*4 = 7168
#define OFF_BS  40960
#define OFF_NBS 49152
#define SMEM_REQ 56320

__global__ __launch_bounds__(256, 2)
void sconv_bf16(const float* __restrict__ x,
                const int* __restrict__ nb,
                const float* __restrict__ bias,
                float* __restrict__ out) {
    extern __shared__ char dsm[];
    float* As  = (float*)dsm;                 // [2][256*SA]
    uint4* Bs  = (uint4*)(dsm + OFF_BS);      // [2][256]
    int*   nbs = (int*)(dsm + OFF_NBS);       // [7][256]
    const uint32_t asb = smem_u32(dsm);
    const uint32_t bsb = asb + OFF_BS;

    const int t    = threadIdx.x;
    const int lane = t & 31;
    const int w    = t >> 5;
    const int g    = lane >> 2;
    const int tig  = lane & 3;
    const int wv   = w << 5;            // warp vertex base (32 v per warp)
    const int batch = blockIdx.y;
    const int v0    = blockIdx.x * TILE_V;
    const long long xbase = (long long)batch * V_TOT;

    // ---- stage neighbor indices: nbs[j*256 + r]
#pragma unroll
    for (int i = 0; i < 7; ++i) {
        int idx = t + (i << 8);
        int r = idx & 255, j = idx >> 8;
        int vv = v0 + r; if (vv >= V_TOT) vv = V_TOT - 1;
        nbs[idx] = nb[vv * 7 + j];
    }
    __syncthreads();

    // acc[rb][nblk][e]: row block rb (rows wv+16rb..+15)
    float acc[2][8][4];
#pragma unroll
    for (int rb = 0; rb < 2; ++rb)
#pragma unroll
        for (int n = 0; n < 8; ++n)
#pragma unroll
            for (int e = 0; e < 4; ++e) acc[rb][n][e] = 0.0f;

    // staging: 1024 (row,quad) tasks over 256 threads x 4
    // prologue: stage chunk 0 (j=0, kb=0)
    {
#pragma unroll
        for (int i = 0; i < 4; ++i) {
            int idx = t + (i << 8);
            int row = idx >> 2, q = idx & 3;
            cpa16(asb + (row * SA + (q << 2)) * 4,
                  x + ((xbase + nbs[row]) << 6) + (q << 2));
        }
        cpa16(bsb + t * 16, (const char*)g_Bf + t * 16);
        asm volatile("cp.async.commit_group;" ::: "memory");
    }

    for (int c = 0; c < NCH; ++c) {
        const int buf = c & 1;

        if (c + 1 < NCH) {
            const int cn = c + 1;
            const int j  = cn >> 2;
            const int kb = (cn & 3) << 4;
            const int bn = cn & 1;
            const uint32_t ad = asb + bn * (TILE_V * SA * 4);
#pragma unroll
            for (int i = 0; i < 4; ++i) {
                int idx = t + (i << 8);
                int row = idx >> 2, q = idx & 3;
                cpa16(ad + (row * SA + (q << 2)) * 4,
                      x + ((xbase + nbs[j * 256 + row]) << 6) + kb + (q << 2));
            }
            cpa16(bsb + bn * 4096 + t * 16, (const char*)g_Bf + cn * 4096 + t * 16);
            asm volatile("cp.async.commit_group;" ::: "memory");
            asm volatile("cp.async.wait_group 1;" ::: "memory");
        } else {
            asm volatile("cp.async.wait_group 0;" ::: "memory");
        }
        __syncthreads();

        // ---- compute chunk c: 2 row blocks share the B fragments
        const float* aB = As + buf * (TILE_V * SA);
        uint32_t ah[2][4], al[2][4];
#pragma unroll
        for (int rb = 0; rb < 2; ++rb) {
            const int r0 = (wv + (rb << 4) + g) * SA;
            const int r1 = r0 + 8 * SA;
            float2 p00 = *reinterpret_cast<const float2*>(aB + r0 + 2 * tig);
            float2 p10 = *reinterpret_cast<const float2*>(aB + r1 + 2 * tig);
            float2 p01 = *reinterpret_cast<const float2*>(aB + r0 + 2 * tig + 8);
            float2 p11 = *reinterpret_cast<const float2*>(aB + r1 + 2 * tig + 8);
            cvt_pair(p00, ah[rb][0], al[rb][0]);
            cvt_pair(p10, ah[rb][1], al[rb][1]);
            cvt_pair(p01, ah[rb][2], al[rb][2]);
            cvt_pair(p11, ah[rb][3], al[rb][3]);
        }

        const uint4* bB = Bs + buf * 256;
#pragma unroll
        for (int nblk = 0; nblk < 8; ++nblk) {
            uint4 bf = bB[(nblk << 5) + lane];
            MMA(acc[0][nblk], ah[0], bf.x, bf.y);
            MMA(acc[0][nblk], ah[0], bf.z, bf.w);
            MMA(acc[0][nblk], al[0], bf.x, bf.y);
            MMA(acc[1][nblk], ah[1], bf.x, bf.y);
            MMA(acc[1][nblk], ah[1], bf.z, bf.w);
            MMA(acc[1][nblk], al[1], bf.x, bf.y);
        }
        __syncthreads();   // done reading buf before it is re-staged
    }

    // ---- epilogue: D frags -> global (+bias)
#pragma unroll
    for (int rb = 0; rb < 2; ++rb) {
        const int vr0 = v0 + wv + (rb << 4) + g;
        const int vr1 = vr0 + 8;
#pragma unroll
        for (int nblk = 0; nblk < 8; ++nblk) {
            const int n = (nblk << 3) + 2 * tig;
            const float2 b2 = *reinterpret_cast<const float2*>(bias + n);
            if (vr0 < V_TOT)
                *reinterpret_cast<float2*>(out + ((xbase + vr0) << 6) + n) =
                    make_float2(acc[rb][nblk][0] + b2.x, acc[rb][nblk][1] + b2.y);
            if (vr1 < V_TOT)
                *reinterpret_cast<float2*>(out + ((xbase + vr1) << 6) + n) =
                    make_float2(acc[rb][nblk][2] + b2.x, acc[rb][nblk][3] + b2.y);
        }
    }
}

extern "C" void kernel_launch(void* const* d_in, const int* in_sizes, int n_in,
                              void* d_out, int out_size) {
    const float* x   = (const float*)d_in[0];   // (2, V, 64) f32
    const int*   nbi = (const int*)d_in[1];     // (V*7,) i32
    const float* W   = (const float*)d_in[2];   // (64, 448) f32
    const float* b   = (const float*)d_in[3];   // (64,) f32
    float*       out = (float*)d_out;           // (2, V, 64) f32

    cudaFuncSetAttribute(sconv_bf16, cudaFuncAttributeMaxDynamicSharedMemorySize, SMEM_REQ);

    pack_B_kernel<<<(NCH * 8 * 32 + 255) / 256, 256>>>(W);

    dim3 grid((V_TOT + TILE_V - 1) / TILE_V, 2);
    sconv_bf16<<<grid, 256, SMEM_REQ>>>(x, nbi, b, out);
}